// round 7
// baseline (speedup 1.0000x reference)
#include <cuda_runtime.h>
#include <cstdint>

// ItemCodeDPQ: out[b,s,m*16+d] = centroids[m, clamp(item_codes[input_ids[b,s], m],0,255), d]
//              zeroed where input_ids[b,s] == 0.  input_ids arrive as int32.
//
// R7: two-phase per warp (16 tokens). Phase A stages the 16 code words with
// 16 independent id->code load chains in flight (codes are ints: cheap regs).
// Phase B does 16 independent L1-hit centroid gathers + streaming stores.
// Zero-id predicate packed into a bitmask so id registers die early.

__global__ void __launch_bounds__(256)
itemcode_dpq_kernel(const int* __restrict__ input_ids,
                    const int* __restrict__ item_codes,
                    const float4* __restrict__ centroids4,
                    float4* __restrict__ out4,
                    int ntok)
{
    const unsigned lane = threadIdx.x & 31u;
    const unsigned sub  = lane >> 2;          // 0..7 : sub-codebook this lane serves
    const unsigned part = lane & 3u;          // 0..3 : float4 within 16-float sub-emb

    const unsigned warp = (blockIdx.x * blockDim.x + threadIdx.x) >> 5;
    const unsigned t0   = warp * 16u;
    if (t0 >= (unsigned)ntok) return;         // ntok = 204800, divisible by 16

    // ---- Phase A: 16 independent id -> code chains, stage codes only ----
    int c[16];
    unsigned zmask = 0u;
    #pragma unroll
    for (int j = 0; j < 16; j++) {
        const unsigned id = (unsigned)__ldg(&input_ids[t0 + (unsigned)j]);
        c[j] = __ldg(&item_codes[id * 8u + sub]);      // 1 sector/warp/token
        zmask |= (id == 0u) ? (1u << j) : 0u;
    }

    // ---- Phase B: 16 independent L1 gathers -> streaming 512B stores ----
    #pragma unroll
    for (int j = 0; j < 16; j++) {
        const unsigned code = (unsigned)min(max(c[j], 0), 255);
        float4 v = __ldg(&centroids4[(sub * 256u + code) * 4u + part]);
        if ((zmask >> j) & 1u) v = make_float4(0.f, 0.f, 0.f, 0.f);
        __stcs(&out4[(t0 + (unsigned)j) * 32u + lane], v);
    }
}

extern "C" void kernel_launch(void* const* d_in, const int* in_sizes, int n_in,
                              void* d_out, int out_size)
{
    const int*    input_ids  = (const int*)d_in[0];     // (1024,200) int32
    const int*    item_codes = (const int*)d_in[1];     // (1e6, 8) int32
    const float4* centroids  = (const float4*)d_in[2];  // (8,256,16) fp32
    float4*       out        = (float4*)d_out;          // (1024,200,128) fp32

    const int ntok = in_sizes[0];   // 204800

    // 16 tokens per warp, 8 warps per 256-thread CTA => 128 tokens per CTA
    int warps = (ntok + 15) / 16;
    int ctas  = (warps + 7) / 8;
    itemcode_dpq_kernel<<<ctas, 256>>>(input_ids, item_codes, centroids,
                                       out, ntok);
}

// round 8
// speedup vs baseline: 1.0158x; 1.0158x over previous
#include <cuda_runtime.h>
#include <cstdint>

// ItemCodeDPQ: out[b,s,m*16+d] = centroids[m, clamp(item_codes[input_ids[b,s], m],0,255), d]
//              zeroed where input_ids[b,s] == 0.  input_ids arrive as int32.
//
// R8: 8 tokens/warp, phase-split (stage 8 code ints -> 8 L1 gathers + stores),
// minimal register footprint for max occupancy. Shuffle-free; __stcs stores;
// 32-bit address math.

__global__ void __launch_bounds__(512)
itemcode_dpq_kernel(const int* __restrict__ input_ids,
                    const int* __restrict__ item_codes,
                    const float4* __restrict__ centroids4,
                    float4* __restrict__ out4,
                    int ntok)
{
    const unsigned lane = threadIdx.x & 31u;
    const unsigned sub  = lane >> 2;          // 0..7 : sub-codebook this lane serves
    const unsigned part = lane & 3u;          // 0..3 : float4 within 16-float sub-emb

    const unsigned warp = (blockIdx.x * blockDim.x + threadIdx.x) >> 5;
    const unsigned t0   = warp * 8u;
    if (t0 >= (unsigned)ntok) return;         // ntok = 204800, divisible by 8

    // ---- Phase A: 8 independent id -> code chains, stage codes only ----
    int c[8];
    unsigned zmask = 0u;
    #pragma unroll
    for (int j = 0; j < 8; j++) {
        const unsigned id = (unsigned)__ldg(&input_ids[t0 + (unsigned)j]);
        c[j] = __ldg(&item_codes[id * 8u + sub]);      // 1 sector/warp/token
        zmask |= (id == 0u) ? (1u << j) : 0u;
    }

    // ---- Phase B: 8 independent L1 gathers -> streaming 512B stores ----
    #pragma unroll
    for (int j = 0; j < 8; j++) {
        const unsigned code = (unsigned)min(max(c[j], 0), 255);
        float4 v = __ldg(&centroids4[(sub * 256u + code) * 4u + part]);
        if ((zmask >> j) & 1u) v = make_float4(0.f, 0.f, 0.f, 0.f);
        __stcs(&out4[(t0 + (unsigned)j) * 32u + lane], v);
    }
}

extern "C" void kernel_launch(void* const* d_in, const int* in_sizes, int n_in,
                              void* d_out, int out_size)
{
    const int*    input_ids  = (const int*)d_in[0];     // (1024,200) int32
    const int*    item_codes = (const int*)d_in[1];     // (1e6, 8) int32
    const float4* centroids  = (const float4*)d_in[2];  // (8,256,16) fp32
    float4*       out        = (float4*)d_out;          // (1024,200,128) fp32

    const int ntok = in_sizes[0];   // 204800

    // 8 tokens per warp, 16 warps per 512-thread CTA => 128 tokens per CTA
    int warps = (ntok + 7) / 8;
    int ctas  = (warps + 15) / 16;
    itemcode_dpq_kernel<<<ctas, 512>>>(input_ids, item_codes, centroids,
                                       out, ntok);
}